// round 13
// baseline (speedup 1.0000x reference)
#include <cuda_runtime.h>
#include <cuda_fp16.h>
#include <cstdint>

#define SDIM 2048
#define BDIM 16
#define DDIM 64
#define DVDIM 512
#define QB 64
#define JT 64
#define NT 512

// ---------------- scratch ---------------------------------------------------
__device__ __half g_Kth[DDIM * SDIM];    // fp16 hi of (m@n^T)/64, [d][s]
__device__ __half g_Ktl[DDIM * SDIM];    // fp16 lo residual
__device__ __half g_Vh[SDIM * DVDIM];    // V fp16, [j][dv]

// ---------------- helpers ---------------------------------------------------
#define CPA16(dst, src)  asm volatile("cp.async.cg.shared.global [%0], [%1], 16;" :: "r"(dst), "l"(src))
#define CPA_COMMIT()     asm volatile("cp.async.commit_group;")
#define CPA_WAIT0()      asm volatile("cp.async.wait_group 0;")
#define CPA_WAIT1()      asm volatile("cp.async.wait_group 1;")
#define CPA_WAIT2()      asm volatile("cp.async.wait_group 2;")

__device__ __forceinline__ uint32_t smem_u32(const void* p) {
    uint32_t a;
    asm("{ .reg .u64 t; cvta.to.shared.u64 t, %1; cvt.u32.u64 %0, t; }" : "=r"(a) : "l"(p));
    return a;
}
__device__ __forceinline__ void ldsm4(uint32_t* r, uint32_t addr) {
    asm volatile("ldmatrix.sync.aligned.m8n8.x4.shared.b16 {%0,%1,%2,%3}, [%4];"
        : "=r"(r[0]), "=r"(r[1]), "=r"(r[2]), "=r"(r[3]) : "r"(addr));
}
__device__ __forceinline__ void ldsm4t(uint32_t* r, uint32_t addr) {
    asm volatile("ldmatrix.sync.aligned.m8n8.x4.trans.shared.b16 {%0,%1,%2,%3}, [%4];"
        : "=r"(r[0]), "=r"(r[1]), "=r"(r[2]), "=r"(r[3]) : "r"(addr));
}
__device__ __forceinline__ void mma16(float* c, const uint32_t* a, uint32_t b0, uint32_t b1) {
    asm volatile("mma.sync.aligned.m16n8k16.row.col.f32.f16.f16.f32 "
        "{%0,%1,%2,%3}, {%4,%5,%6,%7}, {%8,%9}, {%0,%1,%2,%3};"
        : "+f"(c[0]), "+f"(c[1]), "+f"(c[2]), "+f"(c[3])
        : "r"(a[0]), "r"(a[1]), "r"(a[2]), "r"(a[3]), "r"(b0), "r"(b1));
}

// ---------------- threefry2x32, key=(0,42), partitionable ------------------
__device__ __forceinline__ uint2 tf2x32(uint32_t x0, uint32_t x1) {
    const uint32_t K1 = 42u;
    const uint32_t K2 = 0x1BD11BDAu ^ 42u;
#define TFR(r) { x0 += x1; x1 = __funnelshift_l(x1, x1, (r)); x1 ^= x0; }
    x1 += K1;
    TFR(13) TFR(15) TFR(26) TFR(6)
    x0 += K1; x1 += K2 + 1u;
    TFR(17) TFR(29) TFR(16) TFR(24)
    x0 += K2; x1 += 0u + 2u;
    TFR(13) TFR(15) TFR(26) TFR(6)
    x1 += K1 + 3u;
    TFR(17) TFR(29) TFR(16) TFR(24)
    x0 += K1; x1 += K2 + 4u;
    TFR(13) TFR(15) TFR(26) TFR(6)
    x0 += K2; x1 += 0u + 5u;
#undef TFR
    return make_uint2(x0, x1);
}
// keep iff u < 0.75  ⟺  (x^y) < 0xC0000000  (exact integer equivalent)
__device__ __forceinline__ bool keep_mask(uint32_t f) {
    uint2 r = tf2x32(0u, f);
    return (r.x ^ r.y) < 0xC0000000u;
}

// ---------------------------------------------------------------------------
// Kernel 1: K' = (m @ n^T)/64, fp16 hi/lo. grid 128, 256 thr.
//   smm swizzled: value (d,c) stored at smm[d][(c+d)&63] -> conflict-light reads
// ---------------------------------------------------------------------------
__global__ __launch_bounds__(256) void k_build_kt(
    const float* __restrict__ m, const float* __restrict__ n) {
    __shared__ float smm[64][64];
    __shared__ float snn[16][68];
    const int t = threadIdx.x;
    const int s0 = blockIdx.x * 16;
    const int di = (t & 15) * 4, sj = t >> 4;
    float acc[4] = {};
    for (int c0 = 0; c0 < DVDIM; c0 += 64) {
#pragma unroll
        for (int u = 0; u < 4; ++u) {
            int idx = t + u * 256;
            int r = idx >> 4, c4 = (idx & 15) * 4;
            float4 v = *reinterpret_cast<const float4*>(m + (size_t)r * DVDIM + c0 + c4);
            smm[r][(c4 + 0 + r) & 63] = v.x;
            smm[r][(c4 + 1 + r) & 63] = v.y;
            smm[r][(c4 + 2 + r) & 63] = v.z;
            smm[r][(c4 + 3 + r) & 63] = v.w;
        }
        {
            int r = t >> 4, c4 = (t & 15) * 4;
            *reinterpret_cast<float4*>(&snn[r][c4]) =
                *reinterpret_cast<const float4*>(n + (size_t)(s0 + r) * DVDIM + c0 + c4);
        }
        __syncthreads();
#pragma unroll 16
        for (int c = 0; c < 64; ++c) {
            float nv = snn[sj][c];
            acc[0] += smm[di + 0][(c + di + 0) & 63] * nv;
            acc[1] += smm[di + 1][(c + di + 1) & 63] * nv;
            acc[2] += smm[di + 2][(c + di + 2) & 63] * nv;
            acc[3] += smm[di + 3][(c + di + 3) & 63] * nv;
        }
        __syncthreads();
    }
#pragma unroll
    for (int i = 0; i < 4; ++i) {
        float val = acc[i] * (1.0f / 64.0f);
        __half hh = __float2half_rn(val);
        g_Kth[(size_t)(di + i) * SDIM + s0 + sj] = hh;
        g_Ktl[(size_t)(di + i) * SDIM + s0 + sj] = __float2half_rn(val - __half2float(hh));
    }
}

// ---------------------------------------------------------------------------
// Kernel 2: g_Vh = fp16(q)
// ---------------------------------------------------------------------------
__global__ void k_vr(const float* __restrict__ q) {
    const int idx = blockIdx.x * 256 + threadIdx.x;
    float4 v = reinterpret_cast<const float4*>(q)[idx];
    __half2* dst = reinterpret_cast<__half2*>(g_Vh) + idx * 2;
    dst[0] = __floats2half2_rn(v.x, v.y);
    dst[1] = __floats2half2_rn(v.z, v.w);
}

// ---------------------------------------------------------------------------
// Kernel 3: fused attention, software-pipelined.
//   Window i: QK_{i+1}(tensor) + threefry_{i+1}(ALU) + PV_i(tensor) in ONE
//   barrier window -> ALU/tensor overlap via warp drift. K/V/P double-buffered.
// smem (bytes):
//   lf 0(256)  lpart 256(1024)
//   QH 1280  QL 10496                (9216 each)
//   KH0 19712 KL0 28928 KH1 38144 KL1 47360
//   P0 56576  P1 65792
//   V0 75008  V1 141568 (66560 each)  total 208128
// ---------------------------------------------------------------------------
#define OFF_LF 0
#define OFF_LP 256
#define OFF_QH 1280
#define OFF_QL 10496
#define OFF_KH(b) (19712 + (b) * 18432)
#define OFF_KL(b) (19712 + (b) * 18432 + 9216)
#define OFF_P(b)  (56576 + (b) * 9216)
#define OFF_V(b)  (75008 + (b) * 66560)
#define ATT_SMEM 208128
#define HSTR 72
#define P_SC 6.103515625e-05f   // 2^-14
#define P_UNSC 16384.0f

__device__ __forceinline__ void issueK(uint32_t sb, int buf, int j0, int t) {
    int d = t >> 3, c = t & 7;
    uint32_t dsto = (uint32_t)(d * 144 + c * 16);
    CPA16(sb + OFF_KH(buf) + dsto, g_Kth + (size_t)d * SDIM + j0 + c * 8);
    CPA16(sb + OFF_KL(buf) + dsto, g_Ktl + (size_t)d * SDIM + j0 + c * 8);
}
__device__ __forceinline__ void issueV(uint32_t sb, int buf, int j0, int t) {
#pragma unroll
    for (int u = 0; u < 8; ++u) {
        int idx = t + u * NT;
        int jr = idx >> 6, c = idx & 63;
        CPA16(sb + OFF_V(buf) + (uint32_t)(jr * 1040 + c * 16),
              g_Vh + (size_t)(j0 + jr) * DVDIM + c * 8);
    }
}

__global__ __launch_bounds__(NT, 1) void k_attn(
    const float* __restrict__ x1, float* __restrict__ out) {
    extern __shared__ char smem[];
    const uint32_t sb = smem_u32(smem);
    float* lf    = reinterpret_cast<float*>(smem + OFF_LF);
    float* lpart = reinterpret_cast<float*>(smem + OFF_LP);
    __half* sQh  = reinterpret_cast<__half*>(smem + OFF_QH);
    __half* sQl  = reinterpret_cast<__half*>(smem + OFF_QL);

    const int t = threadIdx.x, w = t >> 5, lane = t & 31;
    const int g = lane >> 2, tid = lane & 3;
    const int b = blockIdx.x >> 5;
    const int i0 = (blockIdx.x & 31) << 6;
    const int lrow = lane & 15;
    const int lcol8 = (lane >> 4) * 8;

    if (t < 256) lpart[t] = 0.f;

    // ---- load Q, split fp16 hi/lo ----
    {
        const float* xq = x1 + ((size_t)b * SDIM + i0) * DDIM;
#pragma unroll
        for (int u = 0; u < 2; ++u) {
            int idx = t + u * NT;
            int r = idx >> 4, d4 = (idx & 15) << 2;
            float4 v = *reinterpret_cast<const float4*>(xq + (size_t)r * DDIM + d4);
            __half hx = __float2half_rn(v.x), hy = __float2half_rn(v.y);
            __half hz = __float2half_rn(v.z), hw = __float2half_rn(v.w);
            __half lx = __float2half_rn(v.x - __half2float(hx));
            __half ly = __float2half_rn(v.y - __half2float(hy));
            __half lz = __float2half_rn(v.z - __half2float(hz));
            __half lw = __float2half_rn(v.w - __half2float(hw));
            *reinterpret_cast<__half2*>(sQh + r * HSTR + d4)     = __halves2half2(hx, hy);
            *reinterpret_cast<__half2*>(sQh + r * HSTR + d4 + 2) = __halves2half2(hz, hw);
            *reinterpret_cast<__half2*>(sQl + r * HSTR + d4)     = __halves2half2(lx, ly);
            *reinterpret_cast<__half2*>(sQl + r * HSTR + d4 + 2) = __halves2half2(lz, lw);
        }
    }

    const int m0 = (w & 3) * 16, n0 = (w >> 2) * 16;
    const int colbase = w * 32;

    float acc[4][4][4];
#pragma unroll
    for (int rt = 0; rt < 4; ++rt)
#pragma unroll
        for (int ct = 0; ct < 4; ++ct)
#pragma unroll
            for (int k = 0; k < 4; ++k) acc[rt][ct][k] = 0.f;

    const float psc = (1.0f / 0.75f) * P_SC;
    const uint32_t frow_g  = ((uint32_t)b << 22) | ((uint32_t)(i0 + m0 + g) << 11);
    const uint32_t frow_g8 = frow_g + (8u << 11);

    // ================= QK + softmax + dropout for tile `tl`, buffers kb/pb ==
#define DO_QK_SOFTMAX(tl, kb, pb) do {                                          \
        const int j0_ = (tl) * JT;                                              \
        float cfr[2][4] = {{0.f, 0.f, 0.f, 0.f}, {0.f, 0.f, 0.f, 0.f}};         \
        _Pragma("unroll")                                                       \
        for (int ks = 0; ks < 4; ++ks) {                                        \
            const int k0 = ks * 16;                                             \
            uint32_t ah[4], al[4], bh[4], bl[4];                                \
            uint32_t qoff = (uint32_t)((m0 + lrow) * 144 + (k0 + lcol8) * 2);   \
            ldsm4(ah, sb + OFF_QH + qoff);                                      \
            ldsm4(al, sb + OFF_QL + qoff);                                      \
            uint32_t koff = (uint32_t)((k0 + lrow) * 144 + (n0 + lcol8) * 2);   \
            ldsm4t(bh, sb + OFF_KH(kb) + koff);                                 \
            ldsm4t(bl, sb + OFF_KL(kb) + koff);                                 \
            _Pragma("unroll")                                                   \
            for (int u = 0; u < 2; ++u) {                                       \
                mma16(cfr[u], ah, bh[u * 2], bh[u * 2 + 1]);                    \
                mma16(cfr[u], ah, bl[u * 2], bl[u * 2 + 1]);                    \
                mma16(cfr[u], al, bh[u * 2], bh[u * 2 + 1]);                    \
            }                                                                   \
        }                                                                       \
        float lg = 0.f, lg8 = 0.f;                                              \
        __half* sP_ = reinterpret_cast<__half*>(smem + OFF_P(pb));              \
        _Pragma("unroll")                                                       \
        for (int u = 0; u < 2; ++u) {                                           \
            const uint32_t col = (uint32_t)(j0_ + n0 + u * 8 + 2 * tid);        \
            float p0 = __expf(cfr[u][0]);                                       \
            float p1 = __expf(cfr[u][1]);                                       \
            float p2 = __expf(cfr[u][2]);                                       \
            float p3 = __expf(cfr[u][3]);                                       \
            lg += p0 + p1;                                                      \
            lg8 += p2 + p3;                                                     \
            float v0 = keep_mask(frow_g  | col)       ? p0 * psc : 0.f;         \
            float v1 = keep_mask(frow_g  | (col + 1)) ? p1 * psc : 0.f;         \
            float v2 = keep_mask(frow_g8 | col)       ? p2 * psc : 0.f;         \
            float v3 = keep_mask(frow_g8 | (col + 1)) ? p3 * psc : 0.f;         \
            __half* pb_ = sP_ + (m0 + g) * HSTR + n0 + u * 8 + 2 * tid;         \
            *reinterpret_cast<__half2*>(pb_)            = __floats2half2_rn(v0, v1); \
            *reinterpret_cast<__half2*>(pb_ + 8 * HSTR) = __floats2half2_rn(v2, v3); \
        }                                                                       \
        lg  += __shfl_xor_sync(0xffffffffu, lg, 1);                             \
        lg  += __shfl_xor_sync(0xffffffffu, lg, 2);                             \
        lg8 += __shfl_xor_sync(0xffffffffu, lg8, 1);                            \
        lg8 += __shfl_xor_sync(0xffffffffu, lg8, 2);                            \
        if (tid == 0) {                                                         \
            const int wc = w >> 2;                                              \
            lpart[wc * 64 + m0 + g]     += lg;                                  \
            lpart[wc * 64 + m0 + 8 + g] += lg8;                                 \
        }                                                                       \
    } while (0)

    // ================= PV for buffers pb/vb ================================
#define DO_PV(pb, vb) do {                                                      \
        _Pragma("unroll")                                                       \
        for (int ks = 0; ks < 4; ++ks) {                                        \
            const int k0 = ks * 16;                                             \
            uint32_t ap[4][4];                                                  \
            _Pragma("unroll")                                                   \
            for (int rt = 0; rt < 4; ++rt) {                                    \
                uint32_t poff = (uint32_t)((rt * 16 + lrow) * 144 + (k0 + lcol8) * 2); \
                ldsm4(ap[rt], sb + OFF_P(pb) + poff);                           \
            }                                                                   \
            _Pragma("unroll")                                                   \
            for (int grp = 0; grp < 2; ++grp) {                                 \
                uint32_t bv[4];                                                 \
                uint32_t voff = (uint32_t)((k0 + lrow) * 1040 +                 \
                                           (colbase + grp * 16 + lcol8) * 2);   \
                ldsm4t(bv, sb + OFF_V(vb) + voff);                              \
                _Pragma("unroll")                                               \
                for (int h = 0; h < 2; ++h) {                                   \
                    const int ct = grp * 2 + h;                                 \
                    _Pragma("unroll")                                           \
                    for (int rt = 0; rt < 4; ++rt)                              \
                        mma16(acc[rt][ct], ap[rt], bv[h * 2], bv[h * 2 + 1]);   \
                }                                                               \
            }                                                                   \
        }                                                                       \
    } while (0)

    // ---- prologue: K_0 (group), {K_1, V_0} (group); QK_0 ----
    issueK(sb, 0, 0, t);
    CPA_COMMIT();
    issueK(sb, 1, JT, t);
    issueV(sb, 0, 0, t);
    CPA_COMMIT();
    CPA_WAIT1();          // K_0 done ({K_1,V_0} may be pending)
    __syncthreads();      // K_0 + Q visible
    DO_QK_SOFTMAX(0, 0, 0);

    // ---- main pipeline ----
    for (int i = 0; i < 32; ++i) {
        __syncthreads();  // (1) P_i written; K_i, V_{i-1}, P_{(i+1)&1} free
        if (i <= 29) { issueK(sb, i & 1, (i + 2) * JT, t); CPA_COMMIT(); }
        if (i <= 30) { issueV(sb, (i + 1) & 1, (i + 1) * JT, t); CPA_COMMIT(); }
        if (i <= 29)       CPA_WAIT2();   // K_{i+1}, V_i done
        else if (i == 30)  CPA_WAIT1();
        else               CPA_WAIT0();
        __syncthreads();  // (2) loaded tiles visible to all threads
        if (i < 31) DO_QK_SOFTMAX(i + 1, (i + 1) & 1, (i + 1) & 1);
        DO_PV(i & 1, i & 1);
    }

    // ---- epilogue ----
    __syncthreads();
    if (t < 64) lf[t] = lpart[t] + lpart[64 + t] + lpart[128 + t] + lpart[192 + t];
    __syncthreads();

#pragma unroll
    for (int rt = 0; rt < 4; ++rt) {
        const int r0 = rt * 16 + g;
        const float inv0 = P_UNSC / lf[r0];
        const float inv1 = P_UNSC / lf[r0 + 8];
        float* o0 = out + ((size_t)(b * SDIM + i0 + r0)) * DVDIM;
        float* o1 = out + ((size_t)(b * SDIM + i0 + r0 + 8)) * DVDIM;
#pragma unroll
        for (int ct = 0; ct < 4; ++ct) {
            const int c = colbase + ct * 8 + tid * 2;
            *reinterpret_cast<float2*>(o0 + c) =
                make_float2(acc[rt][ct][0] * inv0, acc[rt][ct][1] * inv0);
            *reinterpret_cast<float2*>(o1 + c) =
                make_float2(acc[rt][ct][2] * inv1, acc[rt][ct][3] * inv1);
        }
    }
#undef DO_QK_SOFTMAX
#undef DO_PV
}

// ---------------------------------------------------------------------------
extern "C" void kernel_launch(void* const* d_in, const int* in_sizes, int n_in,
                              void* d_out, int out_size) {
    const float* x1 = (const float*)d_in[0];  // [16,2048,64]
    const float* m  = (const float*)d_in[1];  // [64,512]
    const float* n  = (const float*)d_in[2];  // [2048,512]
    const float* q  = (const float*)d_in[3];  // [2048,512]
    float* out = (float*)d_out;               // [16,2048,512]

    cudaFuncSetAttribute(k_attn, cudaFuncAttributeMaxDynamicSharedMemorySize, ATT_SMEM);

    k_build_kt<<<SDIM / 16, 256>>>(m, n);
    k_vr<<<SDIM * DVDIM / 1024, 256>>>(q);
    k_attn<<<BDIM * (SDIM / QB), NT, ATT_SMEM>>>(x1, out);
}

// round 14
// speedup vs baseline: 1.0287x; 1.0287x over previous
#include <cuda_runtime.h>
#include <cuda_fp16.h>
#include <cstdint>

#define SDIM 2048
#define BDIM 16
#define DDIM 64
#define DVDIM 512
#define QB 64
#define JT 128
#define NT 512

// ---------------- scratch ---------------------------------------------------
__device__ __half g_Kth[DDIM * SDIM];    // fp16 hi of (m@n^T)/64, [d][s]
__device__ __half g_Ktl[DDIM * SDIM];    // fp16 lo residual
__device__ __half g_Vh[SDIM * DVDIM];    // V fp16, [j][dv]

// ---------------- helpers ---------------------------------------------------
#define CPA16(dst, src)  asm volatile("cp.async.cg.shared.global [%0], [%1], 16;" :: "r"(dst), "l"(src))
#define CPA_COMMIT()     asm volatile("cp.async.commit_group;")
#define CPA_WAIT0()      asm volatile("cp.async.wait_group 0;")
#define CPA_WAIT1()      asm volatile("cp.async.wait_group 1;")

__device__ __forceinline__ uint32_t smem_u32(const void* p) {
    uint32_t a;
    asm("{ .reg .u64 t; cvta.to.shared.u64 t, %1; cvt.u32.u64 %0, t; }" : "=r"(a) : "l"(p));
    return a;
}
__device__ __forceinline__ void ldsm4(uint32_t* r, uint32_t addr) {
    asm volatile("ldmatrix.sync.aligned.m8n8.x4.shared.b16 {%0,%1,%2,%3}, [%4];"
        : "=r"(r[0]), "=r"(r[1]), "=r"(r[2]), "=r"(r[3]) : "r"(addr));
}
__device__ __forceinline__ void ldsm4t(uint32_t* r, uint32_t addr) {
    asm volatile("ldmatrix.sync.aligned.m8n8.x4.trans.shared.b16 {%0,%1,%2,%3}, [%4];"
        : "=r"(r[0]), "=r"(r[1]), "=r"(r[2]), "=r"(r[3]) : "r"(addr));
}
__device__ __forceinline__ void mma16(float* c, const uint32_t* a, uint32_t b0, uint32_t b1) {
    asm volatile("mma.sync.aligned.m16n8k16.row.col.f32.f16.f16.f32 "
        "{%0,%1,%2,%3}, {%4,%5,%6,%7}, {%8,%9}, {%0,%1,%2,%3};"
        : "+f"(c[0]), "+f"(c[1]), "+f"(c[2]), "+f"(c[3])
        : "r"(a[0]), "r"(a[1]), "r"(a[2]), "r"(a[3]), "r"(b0), "r"(b1));
}

// ---------------- threefry2x32, key=(0,42), partitionable ------------------
__device__ __forceinline__ uint2 tf2x32(uint32_t x0, uint32_t x1) {
    const uint32_t K1 = 42u;
    const uint32_t K2 = 0x1BD11BDAu ^ 42u;
#define TFR(r) { x0 += x1; x1 = __funnelshift_l(x1, x1, (r)); x1 ^= x0; }
    x1 += K1;
    TFR(13) TFR(15) TFR(26) TFR(6)
    x0 += K1; x1 += K2 + 1u;
    TFR(17) TFR(29) TFR(16) TFR(24)
    x0 += K2; x1 += 0u + 2u;
    TFR(13) TFR(15) TFR(26) TFR(6)
    x1 += K1 + 3u;
    TFR(17) TFR(29) TFR(16) TFR(24)
    x0 += K1; x1 += K2 + 4u;
    TFR(13) TFR(15) TFR(26) TFR(6)
    x0 += K2; x1 += 0u + 5u;
#undef TFR
    return make_uint2(x0, x1);
}
// keep iff u < 0.75  ⟺  (x^y) < 0xC0000000  (exact integer equivalent)
__device__ __forceinline__ bool keep_mask(uint32_t f) {
    uint2 r = tf2x32(0u, f);
    return (r.x ^ r.y) < 0xC0000000u;
}

// ---------------------------------------------------------------------------
// Kernel 1: K' = (m @ n^T)/64, fp16 hi/lo. grid 128, 256 thr. (swizzled smm)
// ---------------------------------------------------------------------------
__global__ __launch_bounds__(256) void k_build_kt(
    const float* __restrict__ m, const float* __restrict__ n) {
    __shared__ float smm[64][64];
    __shared__ float snn[16][68];
    const int t = threadIdx.x;
    const int s0 = blockIdx.x * 16;
    const int di = (t & 15) * 4, sj = t >> 4;
    float acc[4] = {};
    for (int c0 = 0; c0 < DVDIM; c0 += 64) {
#pragma unroll
        for (int u = 0; u < 4; ++u) {
            int idx = t + u * 256;
            int r = idx >> 4, c4 = (idx & 15) * 4;
            float4 v = *reinterpret_cast<const float4*>(m + (size_t)r * DVDIM + c0 + c4);
            smm[r][(c4 + 0 + r) & 63] = v.x;
            smm[r][(c4 + 1 + r) & 63] = v.y;
            smm[r][(c4 + 2 + r) & 63] = v.z;
            smm[r][(c4 + 3 + r) & 63] = v.w;
        }
        {
            int r = t >> 4, c4 = (t & 15) * 4;
            *reinterpret_cast<float4*>(&snn[r][c4]) =
                *reinterpret_cast<const float4*>(n + (size_t)(s0 + r) * DVDIM + c0 + c4);
        }
        __syncthreads();
#pragma unroll 16
        for (int c = 0; c < 64; ++c) {
            float nv = snn[sj][c];
            acc[0] += smm[di + 0][(c + di + 0) & 63] * nv;
            acc[1] += smm[di + 1][(c + di + 1) & 63] * nv;
            acc[2] += smm[di + 2][(c + di + 2) & 63] * nv;
            acc[3] += smm[di + 3][(c + di + 3) & 63] * nv;
        }
        __syncthreads();
    }
#pragma unroll
    for (int i = 0; i < 4; ++i) {
        float val = acc[i] * (1.0f / 64.0f);
        __half hh = __float2half_rn(val);
        g_Kth[(size_t)(di + i) * SDIM + s0 + sj] = hh;
        g_Ktl[(size_t)(di + i) * SDIM + s0 + sj] = __float2half_rn(val - __half2float(hh));
    }
}

// ---------------------------------------------------------------------------
// Kernel 2: g_Vh = fp16(q)
// ---------------------------------------------------------------------------
__global__ void k_vr(const float* __restrict__ q) {
    const int idx = blockIdx.x * 256 + threadIdx.x;
    float4 v = reinterpret_cast<const float4*>(q)[idx];
    __half2* dst = reinterpret_cast<__half2*>(g_Vh) + idx * 2;
    dst[0] = __floats2half2_rn(v.x, v.y);
    dst[1] = __floats2half2_rn(v.z, v.w);
}

// ---------------------------------------------------------------------------
// Kernel 3: fused attention, JT=128 tiles, single-buffered (R12 structure).
//   QK: fp16 hi/lo split on tensor cores. PV: fp16, P scaled 2^-14.
//   grid 512 (16 b x 32 qblk), 512 threads. 16 j-tiles, 3 barriers each.
// smem (bytes):
//   lf 0 (256)  lpart 256 (1024)
//   QH 1280  QL 10496        (9216 each: 64 x 144B)
//   KH 19712 KL 37120        (17408 each: 64 x 272B)
//   P  54528                 (17408: 64 x 272B)
//   V  71936                 (133120: 128 x 1040B)   total 205056
// ---------------------------------------------------------------------------
#define OFF_LF 0
#define OFF_LP 256
#define OFF_QH 1280
#define OFF_QL 10496
#define OFF_KH 19712
#define OFF_KL 37120
#define OFF_P  54528
#define OFF_V  71936
#define ATT_SMEM 205056
#define QSTRB 144           // Q row stride bytes
#define KSTRB 272           // K/P row stride bytes
#define VSTRB 1040          // V row stride bytes
#define P_SC 6.103515625e-05f   // 2^-14
#define P_UNSC 16384.0f

__global__ __launch_bounds__(NT, 1) void k_attn(
    const float* __restrict__ x1, float* __restrict__ out) {
    extern __shared__ char smem[];
    const uint32_t sb = smem_u32(smem);
    float* lf    = reinterpret_cast<float*>(smem + OFF_LF);
    float* lpart = reinterpret_cast<float*>(smem + OFF_LP);
    __half* sQh  = reinterpret_cast<__half*>(smem + OFF_QH);
    __half* sQl  = reinterpret_cast<__half*>(smem + OFF_QL);
    __half* sP   = reinterpret_cast<__half*>(smem + OFF_P);

    const int t = threadIdx.x, w = t >> 5, lane = t & 31;
    const int g = lane >> 2, tid = lane & 3;
    const int b = blockIdx.x >> 5;
    const int i0 = (blockIdx.x & 31) << 6;
    const int lrow = lane & 15;
    const int lcol8 = (lane >> 4) * 8;

    if (t < 256) lpart[t] = 0.f;

    // ---- load Q, split fp16 hi/lo ----
    {
        const float* xq = x1 + ((size_t)b * SDIM + i0) * DDIM;
#pragma unroll
        for (int u = 0; u < 2; ++u) {
            int idx = t + u * NT;
            int r = idx >> 4, d4 = (idx & 15) << 2;
            float4 v = *reinterpret_cast<const float4*>(xq + (size_t)r * DDIM + d4);
            __half hx = __float2half_rn(v.x), hy = __float2half_rn(v.y);
            __half hz = __float2half_rn(v.z), hw = __float2half_rn(v.w);
            __half lx = __float2half_rn(v.x - __half2float(hx));
            __half ly = __float2half_rn(v.y - __half2float(hy));
            __half lz = __float2half_rn(v.z - __half2float(hz));
            __half lw = __float2half_rn(v.w - __half2float(hw));
            *reinterpret_cast<__half2*>(sQh + r * 72 + d4)     = __halves2half2(hx, hy);
            *reinterpret_cast<__half2*>(sQh + r * 72 + d4 + 2) = __halves2half2(hz, hw);
            *reinterpret_cast<__half2*>(sQl + r * 72 + d4)     = __halves2half2(lx, ly);
            *reinterpret_cast<__half2*>(sQl + r * 72 + d4 + 2) = __halves2half2(lz, lw);
        }
    }
    __syncthreads();

    // QK warp mapping: rows m0 = (w&3)*16, cols n0 = (w>>2)*32 (4 n8-units)
    const int m0 = (w & 3) * 16, n0 = (w >> 2) * 32;
    // PV mapping: warp -> 32 output cols
    const int colbase = w * 32;

    float acc[4][4][4];
#pragma unroll
    for (int rt = 0; rt < 4; ++rt)
#pragma unroll
        for (int ct = 0; ct < 4; ++ct)
#pragma unroll
            for (int k = 0; k < 4; ++k) acc[rt][ct][k] = 0.f;

    const float psc = (1.0f / 0.75f) * P_SC;
    const uint32_t frow_g  = ((uint32_t)b << 22) | ((uint32_t)(i0 + m0 + g) << 11);
    const uint32_t frow_g8 = frow_g + (8u << 11);

    for (int tile = 0; tile < SDIM / JT; ++tile) {
        const int j0 = tile * JT;

        // ---- cp.async: K hi/lo (group A, 2048 ops), V (group B, 8192 ops) ----
#pragma unroll
        for (int u = 0; u < 2; ++u) {
            int idx = t + u * NT;
            int d = idx >> 4, c = idx & 15;
            uint32_t dsto = (uint32_t)(d * KSTRB + c * 16);
            CPA16(sb + OFF_KH + dsto, g_Kth + (size_t)d * SDIM + j0 + c * 8);
            CPA16(sb + OFF_KL + dsto, g_Ktl + (size_t)d * SDIM + j0 + c * 8);
        }
        CPA_COMMIT();
#pragma unroll
        for (int u = 0; u < 16; ++u) {
            int idx = t + u * NT;
            int jr = idx >> 6, c = idx & 63;
            CPA16(sb + OFF_V + (uint32_t)(jr * VSTRB + c * 16),
                  g_Vh + (size_t)(j0 + jr) * DVDIM + c * 8);
        }
        CPA_COMMIT();
        CPA_WAIT1();          // K done (V pending)
        __syncthreads();

        // ---- QK on tensor cores: fp16 split (hh + hl + lh) ----
        float cfr[4][4];
#pragma unroll
        for (int u = 0; u < 4; ++u)
#pragma unroll
            for (int k = 0; k < 4; ++k) cfr[u][k] = 0.f;
#pragma unroll
        for (int ks = 0; ks < 4; ++ks) {
            const int k0 = ks * 16;
            uint32_t ah[4], al[4];
            uint32_t qoff = (uint32_t)((m0 + lrow) * QSTRB + (k0 + lcol8) * 2);
            ldsm4(ah, sb + OFF_QH + qoff);
            ldsm4(al, sb + OFF_QL + qoff);
#pragma unroll
            for (int grp = 0; grp < 2; ++grp) {
                uint32_t bh[4], bl[4];
                uint32_t koff = (uint32_t)((k0 + lrow) * KSTRB +
                                           (n0 + grp * 16 + lcol8) * 2);
                ldsm4t(bh, sb + OFF_KH + koff);
                ldsm4t(bl, sb + OFF_KL + koff);
#pragma unroll
                for (int ul = 0; ul < 2; ++ul) {
                    const int u = grp * 2 + ul;
                    mma16(cfr[u], ah, bh[ul * 2], bh[ul * 2 + 1]);
                    mma16(cfr[u], ah, bl[ul * 2], bl[ul * 2 + 1]);
                    mma16(cfr[u], al, bh[ul * 2], bh[ul * 2 + 1]);
                }
            }
        }

        // ---- exp, dropout, l partials (C: rows m0+g / m0+g+8, cols n0+u*8+2tid) ----
        float lg = 0.f, lg8 = 0.f;
#pragma unroll
        for (int u = 0; u < 4; ++u) {
            const uint32_t col = (uint32_t)(j0 + n0 + u * 8 + 2 * tid);
            float p0 = __expf(cfr[u][0]);
            float p1 = __expf(cfr[u][1]);
            float p2 = __expf(cfr[u][2]);
            float p3 = __expf(cfr[u][3]);
            lg += p0 + p1;
            lg8 += p2 + p3;
            float v0 = keep_mask(frow_g  | col)       ? p0 * psc : 0.f;
            float v1 = keep_mask(frow_g  | (col + 1)) ? p1 * psc : 0.f;
            float v2 = keep_mask(frow_g8 | col)       ? p2 * psc : 0.f;
            float v3 = keep_mask(frow_g8 | (col + 1)) ? p3 * psc : 0.f;
            __half* pb = sP + (m0 + g) * 136 + n0 + u * 8 + 2 * tid;
            *reinterpret_cast<__half2*>(pb)           = __floats2half2_rn(v0, v1);
            *reinterpret_cast<__half2*>(pb + 8 * 136) = __floats2half2_rn(v2, v3);
        }
        lg  += __shfl_xor_sync(0xffffffffu, lg, 1);
        lg  += __shfl_xor_sync(0xffffffffu, lg, 2);
        lg8 += __shfl_xor_sync(0xffffffffu, lg8, 1);
        lg8 += __shfl_xor_sync(0xffffffffu, lg8, 2);
        if (tid == 0) {
            const int wc = w >> 2;
            lpart[wc * 64 + m0 + g]     += lg;
            lpart[wc * 64 + m0 + 8 + g] += lg8;
        }

        CPA_WAIT0();          // V arrived
        __syncthreads();      // P + V visible to all warps

        // ---- PV on tensor cores: O[64x512] += P[64x128] @ V[128x512] ----
#pragma unroll
        for (int ks = 0; ks < 8; ++ks) {
            const int k0 = ks * 16;
            uint32_t ap[4][4];
#pragma unroll
            for (int rt = 0; rt < 4; ++rt) {
                uint32_t poff = (uint32_t)((rt * 16 + lrow) * KSTRB + (k0 + lcol8) * 2);
                ldsm4(ap[rt], sb + OFF_P + poff);
            }
#pragma unroll
            for (int grp = 0; grp < 2; ++grp) {
                uint32_t bv[4];
                uint32_t voff = (uint32_t)((k0 + lrow) * VSTRB +
                                           (colbase + grp * 16 + lcol8) * 2);
                ldsm4t(bv, sb + OFF_V + voff);
#pragma unroll
                for (int h = 0; h < 2; ++h) {
                    const int ct = grp * 2 + h;
#pragma unroll
                    for (int rt = 0; rt < 4; ++rt)
                        mma16(acc[rt][ct], ap[rt], bv[h * 2], bv[h * 2 + 1]);
                }
            }
        }
        __syncthreads();      // done reading K/V/P before next tile's cp.async
    }

    // ---- epilogue ----
    if (t < 64) lf[t] = lpart[t] + lpart[64 + t] + lpart[128 + t] + lpart[192 + t];
    __syncthreads();

#pragma unroll
    for (int rt = 0; rt < 4; ++rt) {
        const int r0 = rt * 16 + g;
        const float inv0 = P_UNSC / lf[r0];
        const float inv1 = P_UNSC / lf[r0 + 8];
        float* o0 = out + ((size_t)(b * SDIM + i0 + r0)) * DVDIM;
        float* o1 = out + ((size_t)(b * SDIM + i0 + r0 + 8)) * DVDIM;
#pragma unroll
        for (int ct = 0; ct < 4; ++ct) {
            const int c = colbase + ct * 8 + tid * 2;
            *reinterpret_cast<float2*>(o0 + c) =
                make_float2(acc[rt][ct][0] * inv0, acc[rt][ct][1] * inv0);
            *reinterpret_cast<float2*>(o1 + c) =
                make_float2(acc[rt][ct][2] * inv1, acc[rt][ct][3] * inv1);
        }
    }
}

// ---------------------------------------------------------------------------
extern "C" void kernel_launch(void* const* d_in, const int* in_sizes, int n_in,
                              void* d_out, int out_size) {
    const float* x1 = (const float*)d_in[0];  // [16,2048,64]
    const float* m  = (const float*)d_in[1];  // [64,512]
    const float* n  = (const float*)d_in[2];  // [2048,512]
    const float* q  = (const float*)d_in[3];  // [2048,512]
    float* out = (float*)d_out;               // [16,2048,512]

    cudaFuncSetAttribute(k_attn, cudaFuncAttributeMaxDynamicSharedMemorySize, ATT_SMEM);

    k_build_kt<<<SDIM / 16, 256>>>(m, n);
    k_vr<<<SDIM * DVDIM / 1024, 256>>>(q);
    k_attn<<<BDIM * (SDIM / QB), NT, ATT_SMEM>>>(x1, out);
}

// round 15
// speedup vs baseline: 1.1625x; 1.1301x over previous
#include <cuda_runtime.h>
#include <cuda_fp16.h>
#include <cstdint>

#define SDIM 2048
#define BDIM 16
#define DDIM 64
#define DVDIM 512
#define QB 32
#define JT 64
#define NT 512

// ---------------- scratch ---------------------------------------------------
__device__ __half g_Kth[DDIM * SDIM];    // fp16 hi of (m@n^T)/64, [d][s]
__device__ __half g_Ktl[DDIM * SDIM];    // fp16 lo residual
__device__ __half g_Vh[SDIM * DVDIM];    // V fp16, [j][dv]

// ---------------- helpers ---------------------------------------------------
#define CPA16(dst, src)  asm volatile("cp.async.cg.shared.global [%0], [%1], 16;" :: "r"(dst), "l"(src))
#define CPA_COMMIT()     asm volatile("cp.async.commit_group;")
#define CPA_WAIT0()      asm volatile("cp.async.wait_group 0;")
#define CPA_WAIT1()      asm volatile("cp.async.wait_group 1;")

__device__ __forceinline__ uint32_t smem_u32(const void* p) {
    uint32_t a;
    asm("{ .reg .u64 t; cvta.to.shared.u64 t, %1; cvt.u32.u64 %0, t; }" : "=r"(a) : "l"(p));
    return a;
}
__device__ __forceinline__ void bar_sync(int id, int cnt) {
    asm volatile("bar.sync %0, %1;" :: "r"(id), "r"(cnt) : "memory");
}
__device__ __forceinline__ void bar_arrive(int id, int cnt) {
    asm volatile("bar.arrive %0, %1;" :: "r"(id), "r"(cnt) : "memory");
}
__device__ __forceinline__ void ldsm4(uint32_t* r, uint32_t addr) {
    asm volatile("ldmatrix.sync.aligned.m8n8.x4.shared.b16 {%0,%1,%2,%3}, [%4];"
        : "=r"(r[0]), "=r"(r[1]), "=r"(r[2]), "=r"(r[3]) : "r"(addr));
}
__device__ __forceinline__ void ldsm4t(uint32_t* r, uint32_t addr) {
    asm volatile("ldmatrix.sync.aligned.m8n8.x4.trans.shared.b16 {%0,%1,%2,%3}, [%4];"
        : "=r"(r[0]), "=r"(r[1]), "=r"(r[2]), "=r"(r[3]) : "r"(addr));
}
__device__ __forceinline__ void mma16(float* c, const uint32_t* a, uint32_t b0, uint32_t b1) {
    asm volatile("mma.sync.aligned.m16n8k16.row.col.f32.f16.f16.f32 "
        "{%0,%1,%2,%3}, {%4,%5,%6,%7}, {%8,%9}, {%0,%1,%2,%3};"
        : "+f"(c[0]), "+f"(c[1]), "+f"(c[2]), "+f"(c[3])
        : "r"(a[0]), "r"(a[1]), "r"(a[2]), "r"(a[3]), "r"(b0), "r"(b1));
}

// ---------------- threefry2x32, key=(0,42), partitionable ------------------
__device__ __forceinline__ uint2 tf2x32(uint32_t x0, uint32_t x1) {
    const uint32_t K1 = 42u;
    const uint32_t K2 = 0x1BD11BDAu ^ 42u;
#define TFR(r) { x0 += x1; x1 = __funnelshift_l(x1, x1, (r)); x1 ^= x0; }
    x1 += K1;
    TFR(13) TFR(15) TFR(26) TFR(6)
    x0 += K1; x1 += K2 + 1u;
    TFR(17) TFR(29) TFR(16) TFR(24)
    x0 += K2; x1 += 0u + 2u;
    TFR(13) TFR(15) TFR(26) TFR(6)
    x1 += K1 + 3u;
    TFR(17) TFR(29) TFR(16) TFR(24)
    x0 += K1; x1 += K2 + 4u;
    TFR(13) TFR(15) TFR(26) TFR(6)
    x0 += K2; x1 += 0u + 5u;
#undef TFR
    return make_uint2(x0, x1);
}
// keep iff u < 0.75  ⟺  (x^y) < 0xC0000000  (exact integer equivalent)
__device__ __forceinline__ bool keep_mask(uint32_t f) {
    uint2 r = tf2x32(0u, f);
    return (r.x ^ r.y) < 0xC0000000u;
}

// ---------------------------------------------------------------------------
// Kernel 1: K' = (m @ n^T)/64, fp16 hi/lo. grid 128, 256 thr. (swizzled smm)
// ---------------------------------------------------------------------------
__global__ __launch_bounds__(256) void k_build_kt(
    const float* __restrict__ m, const float* __restrict__ n) {
    __shared__ float smm[64][64];
    __shared__ float snn[16][68];
    const int t = threadIdx.x;
    const int s0 = blockIdx.x * 16;
    const int di = (t & 15) * 4, sj = t >> 4;
    float acc[4] = {};
    for (int c0 = 0; c0 < DVDIM; c0 += 64) {
#pragma unroll
        for (int u = 0; u < 4; ++u) {
            int idx = t + u * 256;
            int r = idx >> 4, c4 = (idx & 15) * 4;
            float4 v = *reinterpret_cast<const float4*>(m + (size_t)r * DVDIM + c0 + c4);
            smm[r][(c4 + 0 + r) & 63] = v.x;
            smm[r][(c4 + 1 + r) & 63] = v.y;
            smm[r][(c4 + 2 + r) & 63] = v.z;
            smm[r][(c4 + 3 + r) & 63] = v.w;
        }
        {
            int r = t >> 4, c4 = (t & 15) * 4;
            *reinterpret_cast<float4*>(&snn[r][c4]) =
                *reinterpret_cast<const float4*>(n + (size_t)(s0 + r) * DVDIM + c0 + c4);
        }
        __syncthreads();
#pragma unroll 16
        for (int c = 0; c < 64; ++c) {
            float nv = snn[sj][c];
            acc[0] += smm[di + 0][(c + di + 0) & 63] * nv;
            acc[1] += smm[di + 1][(c + di + 1) & 63] * nv;
            acc[2] += smm[di + 2][(c + di + 2) & 63] * nv;
            acc[3] += smm[di + 3][(c + di + 3) & 63] * nv;
        }
        __syncthreads();
    }
#pragma unroll
    for (int i = 0; i < 4; ++i) {
        float val = acc[i] * (1.0f / 64.0f);
        __half hh = __float2half_rn(val);
        g_Kth[(size_t)(di + i) * SDIM + s0 + sj] = hh;
        g_Ktl[(size_t)(di + i) * SDIM + s0 + sj] = __float2half_rn(val - __half2float(hh));
    }
}

// ---------------------------------------------------------------------------
// Kernel 2: g_Vh = fp16(q)
// ---------------------------------------------------------------------------
__global__ void k_vr(const float* __restrict__ q) {
    const int idx = blockIdx.x * 256 + threadIdx.x;
    float4 v = reinterpret_cast<const float4*>(q)[idx];
    __half2* dst = reinterpret_cast<__half2*>(g_Vh) + idx * 2;
    dst[0] = __floats2half2_rn(v.x, v.y);
    dst[1] = __floats2half2_rn(v.z, v.w);
}

// ---------------------------------------------------------------------------
// Kernel 3: warp-specialized fused attention.
//   Warps 0-7 (producers): K cp.async, QK (fp16 hi/lo mma), exp, threefry, P.
//   Warps 8-15 (consumers): V cp.async, PV mma, output.
//   QB=32, JT=64, 32 tiles, grid 1024 (16 b x 64 qblk), 512 threads.
// Named barriers: 1 prod-internal, 2 cons-internal,
//                 3+buf full[buf] (prod arrive / cons sync),
//                 5+buf empty[buf] (cons arrive / prod sync).
// smem (bytes):
//   lf 0 (128)   lpart 128 (512)
//   QH 1024 (4608)  QL 5632 (4608)
//   K bufs @10240: 2 x {KH 9216, KL 9216} = 36864
//   P bufs @47104: 2 x 4608 = 9216
//   V bufs @56320: 2 x 66560 = 133120    total 189440
// ---------------------------------------------------------------------------
#define OFF_LF 0
#define OFF_LP 128
#define OFF_QH 1024
#define OFF_QL 5632
#define OFF_KH(bf) (10240 + (bf) * 18432)
#define OFF_KL(bf) (10240 + (bf) * 18432 + 9216)
#define OFF_P(bf)  (47104 + (bf) * 4608)
#define OFF_V(bf)  (56320 + (bf) * 66560)
#define ATT_SMEM 189440
#define QSTRB 144
#define KSTRB 144
#define PSTRH 72
#define VSTRB 1040
#define P_SC 6.103515625e-05f   // 2^-14
#define P_UNSC 16384.0f
#define NTILE 32

__device__ __forceinline__ void issueK(uint32_t sb, int bf, int j0, int tp) {
#pragma unroll
    for (int u = 0; u < 2; ++u) {
        int idx = tp + u * 256;
        int d = idx >> 3, c = idx & 7;
        uint32_t dsto = (uint32_t)(d * KSTRB + c * 16);
        CPA16(sb + OFF_KH(bf) + dsto, g_Kth + (size_t)d * SDIM + j0 + c * 8);
        CPA16(sb + OFF_KL(bf) + dsto, g_Ktl + (size_t)d * SDIM + j0 + c * 8);
    }
}
__device__ __forceinline__ void issueV(uint32_t sb, int bf, int j0, int tc) {
#pragma unroll
    for (int u = 0; u < 16; ++u) {
        int idx = tc + u * 256;
        int jr = idx >> 6, c = idx & 63;
        CPA16(sb + OFF_V(bf) + (uint32_t)(jr * VSTRB + c * 16),
              g_Vh + (size_t)(j0 + jr) * DVDIM + c * 8);
    }
}

__global__ __launch_bounds__(NT, 1) void k_attn(
    const float* __restrict__ x1, float* __restrict__ out) {
    extern __shared__ char smem[];
    const uint32_t sb = smem_u32(smem);
    float* lf    = reinterpret_cast<float*>(smem + OFF_LF);
    float* lpart = reinterpret_cast<float*>(smem + OFF_LP);
    __half* sQh  = reinterpret_cast<__half*>(smem + OFF_QH);
    __half* sQl  = reinterpret_cast<__half*>(smem + OFF_QL);

    const int t = threadIdx.x, w = t >> 5, lane = t & 31;
    const int g = lane >> 2, tid = lane & 3;
    const int b = blockIdx.x >> 6;
    const int i0 = (blockIdx.x & 63) << 5;
    const int lrow = lane & 15;
    const int lcol8 = (lane >> 4) * 8;

    if (t < 128) lpart[t] = 0.f;

    // ---- all threads: load Q (32 x 64), split fp16 hi/lo ----
    {
        const float* xq = x1 + ((size_t)b * SDIM + i0) * DDIM;
        int r = t >> 4, d4 = (t & 15) << 2;
        float4 v = *reinterpret_cast<const float4*>(xq + (size_t)r * DDIM + d4);
        __half hx = __float2half_rn(v.x), hy = __float2half_rn(v.y);
        __half hz = __float2half_rn(v.z), hw = __float2half_rn(v.w);
        __half lx = __float2half_rn(v.x - __half2float(hx));
        __half ly = __float2half_rn(v.y - __half2float(hy));
        __half lz = __float2half_rn(v.z - __half2float(hz));
        __half lw = __float2half_rn(v.w - __half2float(hw));
        *reinterpret_cast<__half2*>(sQh + r * PSTRH + d4)     = __halves2half2(hx, hy);
        *reinterpret_cast<__half2*>(sQh + r * PSTRH + d4 + 2) = __halves2half2(hz, hw);
        *reinterpret_cast<__half2*>(sQl + r * PSTRH + d4)     = __halves2half2(lx, ly);
        *reinterpret_cast<__half2*>(sQl + r * PSTRH + d4 + 2) = __halves2half2(lz, lw);
    }
    __syncthreads();

    if (w < 8) {
        // =================== PRODUCERS (warps 0-7) ==========================
        const int tp = t;                         // 0..255
        const int m0 = (w & 1) * 16;              // score rows
        const int n0 = (w >> 1) * 16;             // score cols (16 per warp)
        const int wc = w >> 1;
        const float psc = (1.0f / 0.75f) * P_SC;
        const uint32_t frow_g  = ((uint32_t)b << 22) | ((uint32_t)(i0 + m0 + g) << 11);
        const uint32_t frow_g8 = frow_g + (8u << 11);

        issueK(sb, 0, 0, tp);
        CPA_COMMIT();

        for (int i = 0; i < NTILE; ++i) {
            const int j0 = i * JT;
            const int bf = i & 1;
            if (i < NTILE - 1) { issueK(sb, bf ^ 1, j0 + JT, tp); CPA_COMMIT(); }
            if (i < NTILE - 1) CPA_WAIT1(); else CPA_WAIT0();
            bar_sync(1, 256);                     // K(i) visible to producers

            // ---- QK: fp16 split (hh + hl + lh) ----
            float cfr[2][4] = {{0.f, 0.f, 0.f, 0.f}, {0.f, 0.f, 0.f, 0.f}};
#pragma unroll
            for (int ks = 0; ks < 4; ++ks) {
                const int k0 = ks * 16;
                uint32_t ah[4], al[4], bh[4], bl[4];
                uint32_t qoff = (uint32_t)((m0 + lrow) * QSTRB + (k0 + lcol8) * 2);
                ldsm4(ah, sb + OFF_QH + qoff);
                ldsm4(al, sb + OFF_QL + qoff);
                uint32_t koff = (uint32_t)((k0 + lrow) * KSTRB + (n0 + lcol8) * 2);
                ldsm4t(bh, sb + OFF_KH(bf) + koff);
                ldsm4t(bl, sb + OFF_KL(bf) + koff);
#pragma unroll
                for (int u = 0; u < 2; ++u) {
                    mma16(cfr[u], ah, bh[u * 2], bh[u * 2 + 1]);
                    mma16(cfr[u], ah, bl[u * 2], bl[u * 2 + 1]);
                    mma16(cfr[u], al, bh[u * 2], bh[u * 2 + 1]);
                }
            }

            // ---- exp, threefry dropout, l partials ----
            float lg = 0.f, lg8 = 0.f;
            float pvv[2][4];
#pragma unroll
            for (int u = 0; u < 2; ++u) {
                const uint32_t col = (uint32_t)(j0 + n0 + u * 8 + 2 * tid);
                float p0 = __expf(cfr[u][0]);
                float p1 = __expf(cfr[u][1]);
                float p2 = __expf(cfr[u][2]);
                float p3 = __expf(cfr[u][3]);
                lg += p0 + p1;
                lg8 += p2 + p3;
                pvv[u][0] = keep_mask(frow_g  | col)       ? p0 * psc : 0.f;
                pvv[u][1] = keep_mask(frow_g  | (col + 1)) ? p1 * psc : 0.f;
                pvv[u][2] = keep_mask(frow_g8 | col)       ? p2 * psc : 0.f;
                pvv[u][3] = keep_mask(frow_g8 | (col + 1)) ? p3 * psc : 0.f;
            }
            lg  += __shfl_xor_sync(0xffffffffu, lg, 1);
            lg  += __shfl_xor_sync(0xffffffffu, lg, 2);
            lg8 += __shfl_xor_sync(0xffffffffu, lg8, 1);
            lg8 += __shfl_xor_sync(0xffffffffu, lg8, 2);
            if (tid == 0) {
                lpart[wc * 32 + m0 + g]     += lg;
                lpart[wc * 32 + m0 + 8 + g] += lg8;
            }

            if (i >= 2) bar_sync(5 + bf, 512);    // empty[bf]: P(i-2) consumed

            __half* sP = reinterpret_cast<__half*>(smem + OFF_P(bf));
#pragma unroll
            for (int u = 0; u < 2; ++u) {
                __half* pb = sP + (m0 + g) * PSTRH + n0 + u * 8 + 2 * tid;
                *reinterpret_cast<__half2*>(pb)             = __floats2half2_rn(pvv[u][0], pvv[u][1]);
                *reinterpret_cast<__half2*>(pb + 8 * PSTRH) = __floats2half2_rn(pvv[u][2], pvv[u][3]);
            }
            bar_arrive(3 + bf, 512);              // full[bf]: P(i) ready
            bar_sync(1, 256);                     // all producers done tile i
        }
    } else {
        // =================== CONSUMERS (warps 8-15) =========================
        const int tc = t - 256;                   // 0..255
        const int cw = w - 8;
        const int colbase = cw * 64;

        float acc[2][8][4];
#pragma unroll
        for (int rt = 0; rt < 2; ++rt)
#pragma unroll
            for (int ct = 0; ct < 8; ++ct)
#pragma unroll
                for (int k = 0; k < 4; ++k) acc[rt][ct][k] = 0.f;

        issueV(sb, 0, 0, tc);
        CPA_COMMIT();

        for (int i = 0; i < NTILE; ++i) {
            const int bf = i & 1;
            if (i < NTILE - 1) { issueV(sb, bf ^ 1, (i + 1) * JT, tc); CPA_COMMIT(); }
            if (i < NTILE - 1) CPA_WAIT1(); else CPA_WAIT0();
            bar_sync(2, 256);                     // V(i) visible to consumers
            bar_sync(3 + bf, 512);                // full[bf]: P(i) ready

            // ---- PV: O[32x512] += P[32x64] @ V[64x512] ----
#pragma unroll
            for (int ks = 0; ks < 4; ++ks) {
                const int k0 = ks * 16;
                uint32_t ap[2][4];
#pragma unroll
                for (int rt = 0; rt < 2; ++rt) {
                    uint32_t poff = (uint32_t)((rt * 16 + lrow) * (PSTRH * 2) + (k0 + lcol8) * 2);
                    ldsm4(ap[rt], sb + OFF_P(bf) + poff);
                }
#pragma unroll
                for (int grp = 0; grp < 4; ++grp) {
                    uint32_t bv[4];
                    uint32_t voff = (uint32_t)((k0 + lrow) * VSTRB +
                                               (colbase + grp * 16 + lcol8) * 2);
                    ldsm4t(bv, sb + OFF_V(bf) + voff);
#pragma unroll
                    for (int h = 0; h < 2; ++h) {
                        const int ct = grp * 2 + h;
#pragma unroll
                        for (int rt = 0; rt < 2; ++rt)
                            mma16(acc[rt][ct], ap[rt], bv[h * 2], bv[h * 2 + 1]);
                    }
                }
            }
            bar_arrive(5 + bf, 512);              // empty[bf]: P(i) consumed
            bar_sync(2, 256);                     // all consumers done tile i
        }

        // stash acc pointer-free: epilogue below after joint syncs
        __syncthreads();                          // join with producers
        // lf computed by threads t<32 (producers side executes same sync path)
        __syncthreads();

        const float* lfv = lf;
#pragma unroll
        for (int rt = 0; rt < 2; ++rt) {
            const int r0 = rt * 16 + g;
            const float inv0 = P_UNSC / lfv[r0];
            const float inv1 = P_UNSC / lfv[r0 + 8];
            float* o0 = out + ((size_t)(b * SDIM + i0 + r0)) * DVDIM;
            float* o1 = out + ((size_t)(b * SDIM + i0 + r0 + 8)) * DVDIM;
#pragma unroll
            for (int ct = 0; ct < 8; ++ct) {
                const int c = colbase + ct * 8 + tid * 2;
                *reinterpret_cast<float2*>(o0 + c) =
                    make_float2(acc[rt][ct][0] * inv0, acc[rt][ct][1] * inv0);
                *reinterpret_cast<float2*>(o1 + c) =
                    make_float2(acc[rt][ct][2] * inv1, acc[rt][ct][3] * inv1);
            }
        }
        return;
    }

    // producers: join epilogue syncs (must match consumer __syncthreads calls)
    __syncthreads();
    if (t < 32) lf[t] = lpart[t] + lpart[32 + t] + lpart[64 + t] + lpart[96 + t];
    __syncthreads();
}

// ---------------------------------------------------------------------------
extern "C" void kernel_launch(void* const* d_in, const int* in_sizes, int n_in,
                              void* d_out, int out_size) {
    const float* x1 = (const float*)d_in[0];  // [16,2048,64]
    const float* m  = (const float*)d_in[1];  // [64,512]
    const float* n  = (const float*)d_in[2];  // [2048,512]
    const float* q  = (const float*)d_in[3];  // [2048,512]
    float* out = (float*)d_out;               // [16,2048,512]

    cudaFuncSetAttribute(k_attn, cudaFuncAttributeMaxDynamicSharedMemorySize, ATT_SMEM);

    k_build_kt<<<SDIM / 16, 256>>>(m, n);
    k_vr<<<SDIM * DVDIM / 1024, 256>>>(q);
    k_attn<<<BDIM * (SDIM / QB), NT, ATT_SMEM>>>(x1, out);
}